// round 12
// baseline (speedup 1.0000x reference)
#include <cuda_runtime.h>
#include <cuda_bf16.h>
#include <cstdint>

#define BB 8
#define LL 2048
#define PP 32
#define DD 256
#define NXX 16
#define NT (BB*LL)   // 16384 tokens

// ---------------- scratch (device globals; no allocation allowed) ----------------
__device__ float g_h  [NT*DD];
__device__ float g_hn [NT*DD];
__device__ float g_dl2[NT];        // delta * log2(e)
__device__ float g_dB [NT*NXX];    // delta * Bm
__device__ float g_C  [NT*NXX];
__device__ float g_upd[NT*DD];

// ---------------- helpers ----------------
__device__ __forceinline__ float fexp2(float x){
    float r; asm("ex2.approx.f32 %0, %1;" : "=f"(r) : "f"(x)); return r;
}
__device__ __forceinline__ float softplusf(float x){
    return x > 20.f ? x : log1pf(expf(x));
}
__device__ __forceinline__ float geluf(float x){
    return 0.5f * x * (1.f + erff(x * 0.70710678118654752f));
}
__device__ __forceinline__ unsigned long long packdup(float v){
    unsigned long long r; asm("mov.b64 %0, {%1, %1};" : "=l"(r) : "f"(v)); return r;
}
#define FFMA2(acc, a, b) asm("fma.rn.f32x2 %0, %1, %2, %0;" : "+l"(acc) : "l"(a), "l"(b))
__device__ __forceinline__ float2 unpack2(unsigned long long p){
    float lo, hi; asm("mov.b64 {%0, %1}, %2;" : "=f"(lo), "=f"(hi) : "l"(p));
    float2 r; r.x = lo; r.y = hi; return r;
}

// =====================================================================
// K1: fused  h = y@Win + bin ;  hn = LN(h) ;  [delta | B | C] = proj(hn)
// 1024 blocks x 256 threads, 16 tokens/block
// dyn smem: sy[512] | sh[16*256] | shn[16*256] | sw[33*256]  = 68608 B
// =====================================================================
__global__ void __launch_bounds__(256) k1ab(const float* __restrict__ y,
                                            const float* __restrict__ Win,
                                            const float* __restrict__ bin,
                                            const float* __restrict__ ng,
                                            const float* __restrict__ nb,
                                            const float* __restrict__ W_B,
                                            const float* __restrict__ W_C,
                                            const float* __restrict__ qd,
                                            const float* __restrict__ pd){
    extern __shared__ float sm1[];
    float* sy  = sm1;            // [16][32]
    float* sh  = sm1 + 512;      // [16][256]
    float* shn = sm1 + 512 + 4096;   // [16][256]
    float* sw  = sm1 + 512 + 8192;   // [33][256]  row0=q_delta, 1..16=W_B, 17..32=W_C

    int tid  = threadIdx.x;
    int tok0 = blockIdx.x * 16;

    // ---- load y tile + projection weights ----
    sy[tid]       = y[(size_t)tok0*PP + tid];
    sy[tid + 256] = y[(size_t)tok0*PP + tid + 256];
    #pragma unroll
    for (int it = 0; it < 33; it++){
        int idx = tid + it*256;
        int row = idx >> 8, c = idx & 255;
        float v = (row == 0) ? qd[c] : (row <= 16 ? W_B[(row-1)*DD + c]
                                                  : W_C[(row-17)*DD + c]);
        sw[row*DD + c] = v;
    }

    // ---- phase A: h = y @ Win + bin (thread = one d, all 16 tokens) ----
    int d = tid;
    float wcol[PP];
    #pragma unroll
    for (int p = 0; p < PP; p++) wcol[p] = Win[p*DD + d];
    float bi = bin[d];
    __syncthreads();
    #pragma unroll 4
    for (int t = 0; t < 16; t++){
        const float4* yt = (const float4*)&sy[t*PP];
        float h = bi;
        #pragma unroll
        for (int p4 = 0; p4 < 8; p4++){
            float4 yv = yt[p4];
            h = fmaf(wcol[p4*4+0], yv.x, h);
            h = fmaf(wcol[p4*4+1], yv.y, h);
            h = fmaf(wcol[p4*4+2], yv.z, h);
            h = fmaf(wcol[p4*4+3], yv.w, h);
        }
        sh[t*DD + d] = h;
        g_h[(size_t)(tok0 + t)*DD + d] = h;
    }
    __syncthreads();

    // ---- phase LN: warp-per-2-tokens, lane holds 8 d's ----
    {
        int lane = tid & 31, wid = tid >> 5;
        float4 gA = *(const float4*)&ng[lane*8], gB = *(const float4*)&ng[lane*8+4];
        float4 bA = *(const float4*)&nb[lane*8], bB = *(const float4*)&nb[lane*8+4];
        #pragma unroll
        for (int t = 0; t < 2; t++){
            int tok = wid*2 + t;
            float4 h0 = *(const float4*)&sh[tok*DD + lane*8];
            float4 h1 = *(const float4*)&sh[tok*DD + lane*8 + 4];
            float s  = (h0.x+h0.y)+(h0.z+h0.w)+(h1.x+h1.y)+(h1.z+h1.w);
            float s2 = h0.x*h0.x+h0.y*h0.y+h0.z*h0.z+h0.w*h0.w
                     + h1.x*h1.x+h1.y*h1.y+h1.z*h1.z+h1.w*h1.w;
            #pragma unroll
            for (int o = 16; o; o >>= 1){
                s  += __shfl_xor_sync(0xffffffffu, s,  o);
                s2 += __shfl_xor_sync(0xffffffffu, s2, o);
            }
            float mu   = s * (1.f/DD);
            float var  = s2 * (1.f/DD) - mu*mu;
            float rstd = rsqrtf(var + 1e-5f);
            float4 n0, n1;
            n0.x = (h0.x-mu)*rstd*gA.x + bA.x;  n0.y = (h0.y-mu)*rstd*gA.y + bA.y;
            n0.z = (h0.z-mu)*rstd*gA.z + bA.z;  n0.w = (h0.w-mu)*rstd*gA.w + bA.w;
            n1.x = (h1.x-mu)*rstd*gB.x + bB.x;  n1.y = (h1.y-mu)*rstd*gB.y + bB.y;
            n1.z = (h1.z-mu)*rstd*gB.z + bB.z;  n1.w = (h1.w-mu)*rstd*gB.w + bB.w;
            *(float4*)&shn[tok*DD + lane*8]     = n0;
            *(float4*)&shn[tok*DD + lane*8 + 4] = n1;
            *(float4*)&g_hn[(size_t)(tok0+tok)*DD + lane*8]     = n0;
            *(float4*)&g_hn[(size_t)(tok0+tok)*DD + lane*8 + 4] = n1;
        }
    }
    __syncthreads();

    // ---- phase B: 33-row projection, thread = (tok, sub), d = sub*4 + 64j ----
    {
        int tok = tid >> 4, sub = tid & 15;
        unsigned long long ha[8];
        #pragma unroll
        for (int j = 0; j < 4; j++){
            float4 hv = *(const float4*)&shn[tok*DD + sub*4 + 64*j];
            unsigned long long p0, p1;
            asm("mov.b64 %0, {%1, %2};" : "=l"(p0) : "f"(hv.x), "f"(hv.y));
            asm("mov.b64 %0, {%1, %2};" : "=l"(p1) : "f"(hv.z), "f"(hv.w));
            ha[2*j] = p0; ha[2*j+1] = p1;
        }
        unsigned long long acc[33];
        #pragma unroll
        for (int c = 0; c < 33; c++) acc[c] = 0ull;
        #pragma unroll
        for (int c = 0; c < 33; c++){
            #pragma unroll
            for (int j = 0; j < 4; j++){
                ulonglong2 wv = *(const ulonglong2*)&sw[c*DD + sub*4 + 64*j];
                FFMA2(acc[c], ha[2*j],   wv.x);
                FFMA2(acc[c], ha[2*j+1], wv.y);
            }
        }
        float red[33];
        #pragma unroll
        for (int c = 0; c < 33; c++){
            float2 u = unpack2(acc[c]);
            float s = u.x + u.y;
            s += __shfl_xor_sync(0xffffffffu, s, 1);
            s += __shfl_xor_sync(0xffffffffu, s, 2);
            s += __shfl_xor_sync(0xffffffffu, s, 4);
            s += __shfl_xor_sync(0xffffffffu, s, 8);
            red[c] = s;
        }
        if (sub == 0){
            int tg = tok0 + tok;
            float delta = softplusf(pd[0] + red[0]);
            g_dl2[tg] = delta * 1.44269504088896f;
            #pragma unroll
            for (int n = 0; n < NXX; n++) g_dB[tg*NXX + n] = delta * red[1 + n];
            #pragma unroll
            for (int n = 0; n < NXX; n++) g_C[tg*NXX + n] = red[17 + n];
        }
    }
}

// =====================================================================
// K2: selective scan — grid (16 d-chunks, 8 batches) x 256 thr (16d x 16n)
// =====================================================================
__global__ void __launch_bounds__(256) k2(const float* __restrict__ A){
    __shared__ float sdl2[32];
    __shared__ float sdb[32*16];
    __shared__ float sc [32*16];
    __shared__ float su [32*16];
    __shared__ float scx[32*256];
    int tid = threadIdx.x;
    int n = tid & 15, dl = tid >> 4;
    int b = blockIdx.y, d0 = blockIdx.x * 16;
    float a = A[(d0 + dl)*NXX + n];
    float x = 0.f;
    size_t tbase = (size_t)b * LL;

    for (int t0 = 0; t0 < LL; t0 += 32){
        if (tid < 32) sdl2[tid] = g_dl2[tbase + t0 + tid];
        #pragma unroll
        for (int r = 0; r < 2; r++){
            int idx = tid + r*256;
            int tt = idx >> 4, q = idx & 15;
            sdb[idx] = g_dB[(tbase + t0 + tt)*NXX + q];
            sc [idx] = g_C [(tbase + t0 + tt)*NXX + q];
            su [idx] = g_hn[(tbase + t0 + tt)*DD + d0 + q];
        }
        __syncthreads();
        #pragma unroll 4
        for (int tt = 0; tt < 32; tt++){
            float dA  = fexp2(sdl2[tt] * a);
            float dbu = sdb[tt*16 + n] * su[tt*16 + dl];
            x = fmaf(dA, x, dbu);
            scx[tt*256 + dl*16 + n] = x * sc[tt*16 + n];
        }
        __syncthreads();
        #pragma unroll
        for (int r = 0; r < 2; r++){
            int c = tid + r*256;
            int tt = c >> 4, dd = c & 15;
            const float4* p = (const float4*)&scx[tt*256 + dd*16];
            float4 v0 = p[0], v1 = p[1], v2 = p[2], v3 = p[3];
            float s = ((v0.x+v0.y)+(v0.z+v0.w)) + ((v1.x+v1.y)+(v1.z+v1.w))
                    + ((v2.x+v2.y)+(v2.z+v2.w)) + ((v3.x+v3.y)+(v3.z+v3.w));
            g_upd[(tbase + t0 + tt)*DD + d0 + dd] = s;
        }
        __syncthreads();
    }
}

// =====================================================================
// K34: fused  h2 = LN(h+upd) ;  G = gelu(h2@W1+b1) ;  out = G@W2+b2
// 256 blocks (64 tokens each) x 256 threads
// dyn smem: sv[64][260] | Bs[32*256 / W2s 256*32]  = 99328 B
// =====================================================================
#define SVS 260
__global__ void __launch_bounds__(256, 2) k34(const float* __restrict__ nfg,
                                              const float* __restrict__ nfb,
                                              const float* __restrict__ W1,
                                              const float* __restrict__ b1,
                                              const float* __restrict__ W2,
                                              const float* __restrict__ b2,
                                              float* __restrict__ out){
    extern __shared__ float sm3[];
    float* sv = sm3;                 // [64][SVS] : LN result, later gelu result
    float* Bs = sm3 + 64*SVS;        // [32][256] W1 chunk, later [256][32] W2

    int tid  = threadIdx.x;
    int tok0 = blockIdx.x * 64;
    int lane = tid & 31, wrp = tid >> 5;

    // ---- phase 1: LN(h + upd) -> sv. warp wrp handles tokens wrp*8..+7 ----
    {
        float4 gA = *(const float4*)&nfg[lane*8], gB = *(const float4*)&nfg[lane*8+4];
        float4 bA = *(const float4*)&nfb[lane*8], bB = *(const float4*)&nfb[lane*8+4];
        #pragma unroll
        for (int t = 0; t < 8; t++){
            int tok = wrp*8 + t;
            size_t base = (size_t)(tok0 + tok)*DD + lane*8;
            float4 h0 = *(const float4*)&g_h[base];
            float4 h1 = *(const float4*)&g_h[base+4];
            float4 u0 = *(const float4*)&g_upd[base];
            float4 u1 = *(const float4*)&g_upd[base+4];
            float4 v0, v1;
            v0.x=h0.x+u0.x; v0.y=h0.y+u0.y; v0.z=h0.z+u0.z; v0.w=h0.w+u0.w;
            v1.x=h1.x+u1.x; v1.y=h1.y+u1.y; v1.z=h1.z+u1.z; v1.w=h1.w+u1.w;
            float s  = (v0.x+v0.y)+(v0.z+v0.w)+(v1.x+v1.y)+(v1.z+v1.w);
            float s2 = v0.x*v0.x+v0.y*v0.y+v0.z*v0.z+v0.w*v0.w
                     + v1.x*v1.x+v1.y*v1.y+v1.z*v1.z+v1.w*v1.w;
            #pragma unroll
            for (int o = 16; o; o >>= 1){
                s  += __shfl_xor_sync(0xffffffffu, s,  o);
                s2 += __shfl_xor_sync(0xffffffffu, s2, o);
            }
            float mu   = s * (1.f/DD);
            float var  = s2 * (1.f/DD) - mu*mu;
            float rstd = rsqrtf(var + 1e-5f);
            float4 n0, n1;
            n0.x=(v0.x-mu)*rstd*gA.x+bA.x; n0.y=(v0.y-mu)*rstd*gA.y+bA.y;
            n0.z=(v0.z-mu)*rstd*gA.z+bA.z; n0.w=(v0.w-mu)*rstd*gA.w+bA.w;
            n1.x=(v1.x-mu)*rstd*gB.x+bB.x; n1.y=(v1.y-mu)*rstd*gB.y+bB.y;
            n1.z=(v1.z-mu)*rstd*gB.z+bB.z; n1.w=(v1.w-mu)*rstd*gB.w+bB.w;
            *(float4*)&sv[tok*SVS + lane*8]     = n0;
            *(float4*)&sv[tok*SVS + lane*8 + 4] = n1;
        }
    }
    __syncthreads();

    // ---- phase 2: G = gelu(sv @ W1 + b1), tile 64x256, micro 8 tok x 8 col ----
    int tx = tid & 31, ty = tid >> 5;          // cols tx*8..+7 ; toks ty*8..+7
    unsigned long long acc[8][4];
    #pragma unroll
    for (int i = 0; i < 8; i++)
        #pragma unroll
        for (int j = 0; j < 4; j++) acc[i][j] = 0ull;

    for (int kk = 0; kk < DD; kk += 32){
        #pragma unroll
        for (int r = 0; r < 8; r++){
            int f4 = tid + r*256;
            int row = f4 >> 6, c4 = (f4 & 63) << 2;
            *(float4*)&Bs[row*256 + c4] =
                *(const float4*)&W1[(size_t)(kk + row)*DD + c4];
        }
        __syncthreads();
        #pragma unroll 8
        for (int k = 0; k < 32; k++){
            ulonglong2 p0 = *(const ulonglong2*)&Bs[k*256 + tx*8];
            ulonglong2 p1 = *(const ulonglong2*)&Bs[k*256 + tx*8 + 4];
            #pragma unroll
            for (int i = 0; i < 8; i++){
                unsigned long long a2 = packdup(sv[(ty*8+i)*SVS + kk + k]);
                FFMA2(acc[i][0], a2, p0.x);
                FFMA2(acc[i][1], a2, p0.y);
                FFMA2(acc[i][2], a2, p1.x);
                FFMA2(acc[i][3], a2, p1.y);
            }
        }
        __syncthreads();
    }

    // gelu + bias -> back into sv (aliased as G)
    {
        float4 bb0 = *(const float4*)&b1[tx*8];
        float4 bb1 = *(const float4*)&b1[tx*8 + 4];
        float bias[8] = {bb0.x,bb0.y,bb0.z,bb0.w,bb1.x,bb1.y,bb1.z,bb1.w};
        #pragma unroll
        for (int i = 0; i < 8; i++){
            int tok = ty*8 + i;
            #pragma unroll
            for (int j = 0; j < 4; j++){
                float2 u = unpack2(acc[i][j]);
                float2 o;
                o.x = geluf(u.x + bias[2*j]);
                o.y = geluf(u.y + bias[2*j+1]);
                *(float2*)&sv[tok*SVS + tx*8 + 2*j] = o;
            }
        }
    }
    // load W2 into Bs region (linear copy, [256][32])
    #pragma unroll
    for (int r = 0; r < 8; r++){
        int f4 = (tid + r*256) << 2;
        *(float4*)&Bs[f4] = *(const float4*)&W2[f4];
    }
    __syncthreads();

    // ---- phase 3: out = G @ W2 + b2 ; thread = (tok, 8-out group) ----
    {
        int tok = tid >> 2, og = tid & 3;
        float4 c0 = *(const float4*)&b2[og*8];
        float4 c1 = *(const float4*)&b2[og*8 + 4];
        unsigned long long o0, o1, o2, o3;
        asm("mov.b64 %0, {%1, %2};" : "=l"(o0) : "f"(c0.x), "f"(c0.y));
        asm("mov.b64 %0, {%1, %2};" : "=l"(o1) : "f"(c0.z), "f"(c0.w));
        asm("mov.b64 %0, {%1, %2};" : "=l"(o2) : "f"(c1.x), "f"(c1.y));
        asm("mov.b64 %0, {%1, %2};" : "=l"(o3) : "f"(c1.z), "f"(c1.w));
        #pragma unroll 4
        for (int k4 = 0; k4 < DD; k4 += 4){
            float4 g4 = *(const float4*)&sv[tok*SVS + k4];
            float ge[4] = {g4.x, g4.y, g4.z, g4.w};
            #pragma unroll
            for (int e = 0; e < 4; e++){
                unsigned long long a2 = packdup(ge[e]);
                const unsigned long long* wr =
                    (const unsigned long long*)&Bs[(k4 + e)*32 + og*8];
                FFMA2(o0, a2, wr[0]);
                FFMA2(o1, a2, wr[1]);
                FFMA2(o2, a2, wr[2]);
                FFMA2(o3, a2, wr[3]);
            }
        }
        float2 r0 = unpack2(o0), r1 = unpack2(o1), r2 = unpack2(o2), r3 = unpack2(o3);
        float4 w0; w0.x=r0.x; w0.y=r0.y; w0.z=r1.x; w0.w=r1.y;
        float4 w1; w1.x=r2.x; w1.y=r2.y; w1.z=r3.x; w1.w=r3.y;
        size_t ob = (size_t)(tok0 + tok)*32 + og*8;
        *(float4*)&out[ob]     = w0;
        *(float4*)&out[ob + 4] = w1;
    }
}

// ---------------- launcher ----------------
extern "C" void kernel_launch(void* const* d_in, const int* in_sizes, int n_in,
                              void* d_out, int out_size){
    (void)in_sizes; (void)n_in; (void)out_size;
    const float* y    = (const float*)d_in[0];
    const float* Win  = (const float*)d_in[1];
    const float* bin_ = (const float*)d_in[2];
    const float* ng   = (const float*)d_in[3];
    const float* nb   = (const float*)d_in[4];
    const float* A    = (const float*)d_in[5];
    const float* W_B  = (const float*)d_in[6];
    const float* W_C  = (const float*)d_in[7];
    const float* qd   = (const float*)d_in[8];
    const float* pd   = (const float*)d_in[9];
    const float* nfg  = (const float*)d_in[10];
    const float* nfb  = (const float*)d_in[11];
    const float* W1   = (const float*)d_in[12];
    const float* b1   = (const float*)d_in[13];
    const float* W2   = (const float*)d_in[14];
    const float* b2   = (const float*)d_in[15];
    float* out = (float*)d_out;

    cudaFuncSetAttribute(k1ab, cudaFuncAttributeMaxDynamicSharedMemorySize, 68608);
    cudaFuncSetAttribute(k34,  cudaFuncAttributeMaxDynamicSharedMemorySize, 99328);

    k1ab<<<NT/16, 256, 68608>>>(y, Win, bin_, ng, nb, W_B, W_C, qd, pd);
    k2  <<<dim3(DD/16, BB), 256>>>(A);
    k34 <<<NT/64, 256, 99328>>>(nfg, nfb, W1, b1, W2, b2, out);
}

// round 13
// speedup vs baseline: 1.0160x; 1.0160x over previous
#include <cuda_runtime.h>
#include <cuda_bf16.h>
#include <cstdint>

#define BB 8
#define LL 2048
#define PP 32
#define DD 256
#define NXX 16
#define NT (BB*LL)   // 16384 tokens

typedef unsigned long long ull;

// ---------------- scratch (device globals; no allocation allowed) ----------------
__device__ float g_h  [NT*DD];
__device__ float g_hn [NT*DD];
__device__ float g_dl2[NT];        // delta * log2(e)
__device__ float g_dB [NT*NXX];    // delta * Bm
__device__ float g_C  [NT*NXX];
__device__ float g_upd[NT*DD];

// ---------------- helpers ----------------
__device__ __forceinline__ float fexp2(float x){
    float r; asm("ex2.approx.f32 %0, %1;" : "=f"(r) : "f"(x)); return r;
}
__device__ __forceinline__ float softplusf(float x){
    return x > 20.f ? x : log1pf(expf(x));
}
__device__ __forceinline__ float geluf(float x){
    return 0.5f * x * (1.f + erff(x * 0.70710678118654752f));
}
__device__ __forceinline__ ull packdup(float v){
    ull r; asm("mov.b64 %0, {%1, %1};" : "=l"(r) : "f"(v)); return r;
}
#define FFMA2(acc, a, b) asm("fma.rn.f32x2 %0, %1, %2, %0;" : "+l"(acc) : "l"(a), "l"(b))
__device__ __forceinline__ float2 unpack2(ull p){
    float lo, hi; asm("mov.b64 {%0, %1}, %2;" : "=f"(lo), "=f"(hi) : "l"(p));
    float2 r; r.x = lo; r.y = hi; return r;
}

// =====================================================================
// K1: fused  h = y@Win + bin ;  hn = LN(h) ;  [delta | B | C] = proj(hn)
// 1024 blocks x 256 threads, 16 tokens/block
// dyn smem (floats): sy[512] | sh[4096] | shn[4096] | swp[8192] | sqd[256]
//   = 17152 floats = 68608 B
// swp is ull[128][32]: swp[kk][col] = (W[col][2kk], W[col][2kk+1]),
//   cols 0..15 = W_B rows, 16..31 = W_C rows
// =====================================================================
__global__ void __launch_bounds__(256, 3) k1ab(const float* __restrict__ y,
                                               const float* __restrict__ Win,
                                               const float* __restrict__ bin,
                                               const float* __restrict__ ng,
                                               const float* __restrict__ nb,
                                               const float* __restrict__ W_B,
                                               const float* __restrict__ W_C,
                                               const float* __restrict__ qd,
                                               const float* __restrict__ pd){
    extern __shared__ float sm1[];
    float* sy  = sm1;               // [16][32]
    float* sh  = sm1 + 512;         // [16][256]
    float* shn = sm1 + 4608;        // [16][256]
    ull*   swp = (ull*)(sm1 + 8704);// [128][32] packed weight pairs
    float* sqd = sm1 + 16896;       // [256]

    int tid  = threadIdx.x;
    int tok0 = blockIdx.x * 16;

    // ---- load y tile, q_delta, packed/transposed projection weights ----
    sy[tid]       = y[(size_t)tok0*PP + tid];
    sy[tid + 256] = y[(size_t)tok0*PP + tid + 256];
    sqd[tid] = qd[tid];
    {
        int col = tid & 31, kb = (tid >> 5) * 16;
        const float* wrow = (col < 16) ? (W_B + col*DD) : (W_C + (col-16)*DD);
        #pragma unroll
        for (int i = 0; i < 16; i++){
            int kk = kb + i;
            ull v = *(const ull*)&wrow[2*kk];    // (w[2kk], w[2kk+1])
            swp[kk*32 + col] = v;                // lanes=col consecutive: conflict-free STS
        }
    }
    float pd0 = pd[0];

    // ---- phase A: h = y @ Win + bin (thread = one d, all 16 tokens) ----
    int d = tid;
    float wcol[PP];
    #pragma unroll
    for (int p = 0; p < PP; p++) wcol[p] = Win[p*DD + d];
    float bi = bin[d];
    __syncthreads();
    #pragma unroll 4
    for (int t = 0; t < 16; t++){
        const float4* yt = (const float4*)&sy[t*PP];
        float h = bi;
        #pragma unroll
        for (int p4 = 0; p4 < 8; p4++){
            float4 yv = yt[p4];
            h = fmaf(wcol[p4*4+0], yv.x, h);
            h = fmaf(wcol[p4*4+1], yv.y, h);
            h = fmaf(wcol[p4*4+2], yv.z, h);
            h = fmaf(wcol[p4*4+3], yv.w, h);
        }
        sh[t*DD + d] = h;
        g_h[(size_t)(tok0 + t)*DD + d] = h;
    }
    __syncthreads();

    // ---- phase LN: warp-per-2-tokens, lane holds 8 d's ----
    int lane = tid & 31, wid = tid >> 5;
    {
        float4 gA = *(const float4*)&ng[lane*8], gB = *(const float4*)&ng[lane*8+4];
        float4 bA = *(const float4*)&nb[lane*8], bB = *(const float4*)&nb[lane*8+4];
        #pragma unroll
        for (int t = 0; t < 2; t++){
            int tok = wid*2 + t;
            float4 h0 = *(const float4*)&sh[tok*DD + lane*8];
            float4 h1 = *(const float4*)&sh[tok*DD + lane*8 + 4];
            float s  = (h0.x+h0.y)+(h0.z+h0.w)+(h1.x+h1.y)+(h1.z+h1.w);
            float s2 = h0.x*h0.x+h0.y*h0.y+h0.z*h0.z+h0.w*h0.w
                     + h1.x*h1.x+h1.y*h1.y+h1.z*h1.z+h1.w*h1.w;
            #pragma unroll
            for (int o = 16; o; o >>= 1){
                s  += __shfl_xor_sync(0xffffffffu, s,  o);
                s2 += __shfl_xor_sync(0xffffffffu, s2, o);
            }
            float mu   = s * (1.f/DD);
            float var  = s2 * (1.f/DD) - mu*mu;
            float rstd = rsqrtf(var + 1e-5f);
            float4 n0, n1;
            n0.x = (h0.x-mu)*rstd*gA.x + bA.x;  n0.y = (h0.y-mu)*rstd*gA.y + bA.y;
            n0.z = (h0.z-mu)*rstd*gA.z + bA.z;  n0.w = (h0.w-mu)*rstd*gA.w + bA.w;
            n1.x = (h1.x-mu)*rstd*gB.x + bB.x;  n1.y = (h1.y-mu)*rstd*gB.y + bB.y;
            n1.z = (h1.z-mu)*rstd*gB.z + bB.z;  n1.w = (h1.w-mu)*rstd*gB.w + bB.w;
            *(float4*)&shn[tok*DD + lane*8]     = n0;
            *(float4*)&shn[tok*DD + lane*8 + 4] = n1;
            *(float4*)&g_hn[(size_t)(tok0+tok)*DD + lane*8]     = n0;
            *(float4*)&g_hn[(size_t)(tok0+tok)*DD + lane*8 + 4] = n1;
        }
    }
    __syncthreads();

    // ---- phase B: warp = 2 tokens, lane = output column (16 B + 16 C) ----
    {
        const ull* wc = swp + lane;    // this lane's column, stride 32 ull
        #pragma unroll
        for (int t = 0; t < 2; t++){
            int tok = wid*2 + t;
            const float* hrow = &shn[tok*DD];
            // delta: lane-sliced dot hn . q_delta, full warp reduce (broadcast)
            float4 ha = *(const float4*)&hrow[lane*8];
            float4 hb = *(const float4*)&hrow[lane*8 + 4];
            float4 qa = *(const float4*)&sqd[lane*8];
            float4 qb = *(const float4*)&sqd[lane*8 + 4];
            float dsum = ha.x*qa.x + ha.y*qa.y + ha.z*qa.z + ha.w*qa.w
                       + hb.x*qb.x + hb.y*qb.y + hb.z*qb.z + hb.w*qb.w;
            #pragma unroll
            for (int o = 16; o; o >>= 1)
                dsum += __shfl_xor_sync(0xffffffffu, dsum, o);
            float delta = softplusf(pd0 + dsum);

            // B/C column dot: packed over k, two accumulators for ILP
            const ull* hp = (const ull*)hrow;   // hp[kk] = (hn[2kk], hn[2kk+1])
            ull acc0 = 0ull, acc1 = 0ull;
            #pragma unroll 8
            for (int kk = 0; kk < 128; kk += 2){
                ulonglong2 hv = *(const ulonglong2*)&hp[kk];  // broadcast
                FFMA2(acc0, hv.x, wc[kk*32]);
                FFMA2(acc1, hv.y, wc[(kk+1)*32]);
            }
            float2 u = unpack2(acc0), v = unpack2(acc1);
            float s = (u.x + u.y) + (v.x + v.y);

            int tg = tok0 + tok;
            if (lane < 16)       g_dB[tg*NXX + lane]        = delta * s;
            else                 g_C [tg*NXX + (lane - 16)] = s;
            if (lane == 0)       g_dl2[tg] = delta * 1.44269504088896f;
        }
    }
}

// =====================================================================
// K2: selective scan — grid (16 d-chunks, 8 batches) x 256 thr (16d x 16n)
// register double-buffer of the per-tile inputs to hide LDG latency
// =====================================================================
__global__ void __launch_bounds__(256) k2(const float* __restrict__ A){
    __shared__ float sdl2[32];
    __shared__ float sdb[32*16];
    __shared__ float sc [32*16];
    __shared__ float su [32*16];
    __shared__ float scx[32*256];
    int tid = threadIdx.x;
    int n = tid & 15, dl = tid >> 4;
    int b = blockIdx.y, d0 = blockIdx.x * 16;
    float a = A[(d0 + dl)*NXX + n];
    float x = 0.f;
    size_t tbase = (size_t)b * LL;

    // prefetch tile 0 into registers
    float pdb[2], pc[2], pu[2], pdl = 0.f;
    if (tid < 32) pdl = g_dl2[tbase + tid];
    #pragma unroll
    for (int r = 0; r < 2; r++){
        int idx = tid + r*256;
        int tt = idx >> 4, q = idx & 15;
        pdb[r] = g_dB[(tbase + tt)*NXX + q];
        pc [r] = g_C [(tbase + tt)*NXX + q];
        pu [r] = g_hn[(tbase + tt)*DD + d0 + q];
    }

    for (int t0 = 0; t0 < LL; t0 += 32){
        if (tid < 32) sdl2[tid] = pdl;
        #pragma unroll
        for (int r = 0; r < 2; r++){
            int idx = tid + r*256;
            sdb[idx] = pdb[r]; sc[idx] = pc[r]; su[idx] = pu[r];
        }
        __syncthreads();
        // prefetch next tile (overlaps with compute below)
        if (t0 + 32 < LL){
            int t1 = t0 + 32;
            if (tid < 32) pdl = g_dl2[tbase + t1 + tid];
            #pragma unroll
            for (int r = 0; r < 2; r++){
                int idx = tid + r*256;
                int tt = idx >> 4, q = idx & 15;
                pdb[r] = g_dB[(tbase + t1 + tt)*NXX + q];
                pc [r] = g_C [(tbase + t1 + tt)*NXX + q];
                pu [r] = g_hn[(tbase + t1 + tt)*DD + d0 + q];
            }
        }
        #pragma unroll 4
        for (int tt = 0; tt < 32; tt++){
            float dA  = fexp2(sdl2[tt] * a);
            float dbu = sdb[tt*16 + n] * su[tt*16 + dl];
            x = fmaf(dA, x, dbu);
            scx[tt*256 + dl*16 + n] = x * sc[tt*16 + n];
        }
        __syncthreads();
        #pragma unroll
        for (int r = 0; r < 2; r++){
            int c = tid + r*256;
            int tt = c >> 4, dd = c & 15;
            const float4* p = (const float4*)&scx[tt*256 + dd*16];
            float4 v0 = p[0], v1 = p[1], v2 = p[2], v3 = p[3];
            float s = ((v0.x+v0.y)+(v0.z+v0.w)) + ((v1.x+v1.y)+(v1.z+v1.w))
                    + ((v2.x+v2.y)+(v2.z+v2.w)) + ((v3.x+v3.y)+(v3.z+v3.w));
            g_upd[(tbase + t0 + tt)*DD + d0 + dd] = s;
        }
        __syncthreads();
    }
}

// =====================================================================
// K34: fused  h2 = LN(h+upd) ;  G = gelu(h2@W1+b1) ;  out = G@W2+b2
// 256 blocks (64 tokens each) x 256 threads
// dyn smem: sv[64][260] | Bs[32*256 / W2s 256*32]  = 99328 B
// =====================================================================
#define SVS 260
__global__ void __launch_bounds__(256, 2) k34(const float* __restrict__ nfg,
                                              const float* __restrict__ nfb,
                                              const float* __restrict__ W1,
                                              const float* __restrict__ b1,
                                              const float* __restrict__ W2,
                                              const float* __restrict__ b2,
                                              float* __restrict__ out){
    extern __shared__ float sm3[];
    float* sv = sm3;                 // [64][SVS] : LN result, later gelu result
    float* Bs = sm3 + 64*SVS;        // [32][256] W1 chunk, later [256][32] W2

    int tid  = threadIdx.x;
    int tok0 = blockIdx.x * 64;
    int lane = tid & 31, wrp = tid >> 5;

    // ---- phase 1: LN(h + upd) -> sv. warp wrp handles tokens wrp*8..+7 ----
    {
        float4 gA = *(const float4*)&nfg[lane*8], gB = *(const float4*)&nfg[lane*8+4];
        float4 bA = *(const float4*)&nfb[lane*8], bB = *(const float4*)&nfb[lane*8+4];
        #pragma unroll
        for (int t = 0; t < 8; t++){
            int tok = wrp*8 + t;
            size_t base = (size_t)(tok0 + tok)*DD + lane*8;
            float4 h0 = *(const float4*)&g_h[base];
            float4 h1 = *(const float4*)&g_h[base+4];
            float4 u0 = *(const float4*)&g_upd[base];
            float4 u1 = *(const float4*)&g_upd[base+4];
            float4 v0, v1;
            v0.x=h0.x+u0.x; v0.y=h0.y+u0.y; v0.z=h0.z+u0.z; v0.w=h0.w+u0.w;
            v1.x=h1.x+u1.x; v1.y=h1.y+u1.y; v1.z=h1.z+u1.z; v1.w=h1.w+u1.w;
            float s  = (v0.x+v0.y)+(v0.z+v0.w)+(v1.x+v1.y)+(v1.z+v1.w);
            float s2 = v0.x*v0.x+v0.y*v0.y+v0.z*v0.z+v0.w*v0.w
                     + v1.x*v1.x+v1.y*v1.y+v1.z*v1.z+v1.w*v1.w;
            #pragma unroll
            for (int o = 16; o; o >>= 1){
                s  += __shfl_xor_sync(0xffffffffu, s,  o);
                s2 += __shfl_xor_sync(0xffffffffu, s2, o);
            }
            float mu   = s * (1.f/DD);
            float var  = s2 * (1.f/DD) - mu*mu;
            float rstd = rsqrtf(var + 1e-5f);
            float4 n0, n1;
            n0.x=(v0.x-mu)*rstd*gA.x+bA.x; n0.y=(v0.y-mu)*rstd*gA.y+bA.y;
            n0.z=(v0.z-mu)*rstd*gA.z+bA.z; n0.w=(v0.w-mu)*rstd*gA.w+bA.w;
            n1.x=(v1.x-mu)*rstd*gB.x+bB.x; n1.y=(v1.y-mu)*rstd*gB.y+bB.y;
            n1.z=(v1.z-mu)*rstd*gB.z+bB.z; n1.w=(v1.w-mu)*rstd*gB.w+bB.w;
            *(float4*)&sv[tok*SVS + lane*8]     = n0;
            *(float4*)&sv[tok*SVS + lane*8 + 4] = n1;
        }
    }
    __syncthreads();

    // ---- phase 2: G = gelu(sv @ W1 + b1), tile 64x256, micro 8 tok x 8 col ----
    int tx = tid & 31, ty = tid >> 5;          // cols tx*8..+7 ; toks ty*8..+7
    ull acc[8][4];
    #pragma unroll
    for (int i = 0; i < 8; i++)
        #pragma unroll
        for (int j = 0; j < 4; j++) acc[i][j] = 0ull;

    for (int kk = 0; kk < DD; kk += 32){
        #pragma unroll
        for (int r = 0; r < 8; r++){
            int f4 = tid + r*256;
            int row = f4 >> 6, c4 = (f4 & 63) << 2;
            *(float4*)&Bs[row*256 + c4] =
                *(const float4*)&W1[(size_t)(kk + row)*DD + c4];
        }
        __syncthreads();
        #pragma unroll 8
        for (int k = 0; k < 32; k++){
            ulonglong2 p0 = *(const ulonglong2*)&Bs[k*256 + tx*8];
            ulonglong2 p1 = *(const ulonglong2*)&Bs[k*256 + tx*8 + 4];
            #pragma unroll
            for (int i = 0; i < 8; i++){
                ull a2 = packdup(sv[(ty*8+i)*SVS + kk + k]);
                FFMA2(acc[i][0], a2, p0.x);
                FFMA2(acc[i][1], a2, p0.y);
                FFMA2(acc[i][2], a2, p1.x);
                FFMA2(acc[i][3], a2, p1.y);
            }
        }
        __syncthreads();
    }

    // gelu + bias -> back into sv (aliased as G)
    {
        float4 bb0 = *(const float4*)&b1[tx*8];
        float4 bb1 = *(const float4*)&b1[tx*8 + 4];
        float bias[8] = {bb0.x,bb0.y,bb0.z,bb0.w,bb1.x,bb1.y,bb1.z,bb1.w};
        #pragma unroll
        for (int i = 0; i < 8; i++){
            int tok = ty*8 + i;
            #pragma unroll
            for (int j = 0; j < 4; j++){
                float2 u = unpack2(acc[i][j]);
                float2 o;
                o.x = geluf(u.x + bias[2*j]);
                o.y = geluf(u.y + bias[2*j+1]);
                *(float2*)&sv[tok*SVS + tx*8 + 2*j] = o;
            }
        }
    }
    // load W2 into Bs region (linear copy, [256][32])
    #pragma unroll
    for (int r = 0; r < 8; r++){
        int f4 = (tid + r*256) << 2;
        *(float4*)&Bs[f4] = *(const float4*)&W2[f4];
    }
    __syncthreads();

    // ---- phase 3: out = G @ W2 + b2 ; thread = (tok, 8-out group) ----
    {
        int tok = tid >> 2, og = tid & 3;
        float4 c0 = *(const float4*)&b2[og*8];
        float4 c1 = *(const float4*)&b2[og*8 + 4];
        ull o0, o1, o2, o3;
        asm("mov.b64 %0, {%1, %2};" : "=l"(o0) : "f"(c0.x), "f"(c0.y));
        asm("mov.b64 %0, {%1, %2};" : "=l"(o1) : "f"(c0.z), "f"(c0.w));
        asm("mov.b64 %0, {%1, %2};" : "=l"(o2) : "f"(c1.x), "f"(c1.y));
        asm("mov.b64 %0, {%1, %2};" : "=l"(o3) : "f"(c1.z), "f"(c1.w));
        #pragma unroll 4
        for (int k4 = 0; k4 < DD; k4 += 4){
            float4 g4 = *(const float4*)&sv[tok*SVS + k4];
            float ge[4] = {g4.x, g4.y, g4.z, g4.w};
            #pragma unroll
            for (int e = 0; e < 4; e++){
                ull a2 = packdup(ge[e]);
                const ull* wr = (const ull*)&Bs[(k4 + e)*32 + og*8];
                FFMA2(o0, a2, wr[0]);
                FFMA2(o1, a2, wr[1]);
                FFMA2(o2, a2, wr[2]);
                FFMA2(o3, a2, wr[3]);
            }
        }
        float2 r0 = unpack2(o0), r1 = unpack2(o1), r2 = unpack2(o2), r3 = unpack2(o3);
        float4 w0; w0.x=r0.x; w0.y=r0.y; w0.z=r1.x; w0.w=r1.y;
        float4 w1; w1.x=r2.x; w1.y=r2.y; w1.z=r3.x; w1.w=r3.y;
        size_t ob = (size_t)(tok0 + tok)*32 + og*8;
        *(float4*)&out[ob]     = w0;
        *(float4*)&out[ob + 4] = w1;
    }
}

// ---------------- launcher ----------------
extern "C" void kernel_launch(void* const* d_in, const int* in_sizes, int n_in,
                              void* d_out, int out_size){
    (void)in_sizes; (void)n_in; (void)out_size;
    const float* y    = (const float*)d_in[0];
    const float* Win  = (const float*)d_in[1];
    const float* bin_ = (const float*)d_in[2];
    const float* ng   = (const float*)d_in[3];
    const float* nb   = (const float*)d_in[4];
    const float* A    = (const float*)d_in[5];
    const float* W_B  = (const float*)d_in[6];
    const float* W_C  = (const float*)d_in[7];
    const float* qd   = (const float*)d_in[8];
    const float* pd   = (const float*)d_in[9];
    const float* nfg  = (const float*)d_in[10];
    const float* nfb  = (const float*)d_in[11];
    const float* W1   = (const float*)d_in[12];
    const float* b1   = (const float*)d_in[13];
    const float* W2   = (const float*)d_in[14];
    const float* b2   = (const float*)d_in[15];
    float* out = (float*)d_out;

    cudaFuncSetAttribute(k1ab, cudaFuncAttributeMaxDynamicSharedMemorySize, 68608);
    cudaFuncSetAttribute(k34,  cudaFuncAttributeMaxDynamicSharedMemorySize, 99328);

    k1ab<<<NT/16, 256, 68608>>>(y, Win, bin_, ng, nb, W_B, W_C, qd, pd);
    k2  <<<dim3(DD/16, BB), 256>>>(A);
    k34 <<<NT/64, 256, 99328>>>(nfg, nfb, W1, b1, W2, b2, out);
}

// round 14
// speedup vs baseline: 1.0999x; 1.0826x over previous
#include <cuda_runtime.h>
#include <cuda_bf16.h>
#include <cstdint>

#define BB 8
#define LL 2048
#define PP 32
#define DD 256
#define NXX 16
#define NT (BB*LL)   // 16384 tokens

typedef unsigned long long ull;

// ---------------- scratch (device globals; no allocation allowed) ----------------
__device__ float g_h  [NT*DD];
__device__ float g_hn [NT*DD];
__device__ float g_dl2[NT];        // delta * log2(e)
__device__ float g_dB [NT*NXX];    // delta * Bm
__device__ float g_C  [NT*NXX];
__device__ float g_upd[NT*DD];

// ---------------- helpers ----------------
__device__ __forceinline__ float fexp2(float x){
    float r; asm("ex2.approx.f32 %0, %1;" : "=f"(r) : "f"(x)); return r;
}
__device__ __forceinline__ float softplusf(float x){
    return x > 20.f ? x : log1pf(expf(x));
}
__device__ __forceinline__ float geluf(float x){
    return 0.5f * x * (1.f + erff(x * 0.70710678118654752f));
}
__device__ __forceinline__ ull packdup(float v){
    ull r; asm("mov.b64 %0, {%1, %1};" : "=l"(r) : "f"(v)); return r;
}
#define FFMA2(acc, a, b) asm("fma.rn.f32x2 %0, %1, %2, %0;" : "+l"(acc) : "l"(a), "l"(b))
__device__ __forceinline__ float2 unpack2(ull p){
    float lo, hi; asm("mov.b64 {%0, %1}, %2;" : "=f"(lo), "=f"(hi) : "l"(p));
    float2 r; r.x = lo; r.y = hi; return r;
}

// =====================================================================
// K1: fused  h = y@Win + bin ;  hn = LN(h) ;  [delta | B | C] = proj(hn)
// 1024 blocks x 256 threads, 16 tokens/block
// dyn smem (floats): sy[512] | sh[4096] | shn[4096] | sw[33*256]
//   = 17152 floats = 68608 B
// =====================================================================
__global__ void __launch_bounds__(256, 3) k1ab(const float* __restrict__ y,
                                               const float* __restrict__ Win,
                                               const float* __restrict__ bin,
                                               const float* __restrict__ ng,
                                               const float* __restrict__ nb,
                                               const float* __restrict__ W_B,
                                               const float* __restrict__ W_C,
                                               const float* __restrict__ qd,
                                               const float* __restrict__ pd){
    extern __shared__ float sm1[];
    float* sy  = sm1;               // [16][32]
    float* sh  = sm1 + 512;         // [16][256]
    float* shn = sm1 + 4608;        // [16][256]
    float* sw  = sm1 + 8704;        // [33][256]  row0=q_delta, 1..16=W_B, 17..32=W_C

    int tid  = threadIdx.x;
    int tok0 = blockIdx.x * 16;

    // ---- load y tile + projection weights (plain row-major, coalesced) ----
    sy[tid]       = y[(size_t)tok0*PP + tid];
    sy[tid + 256] = y[(size_t)tok0*PP + tid + 256];
    #pragma unroll
    for (int it = 0; it < 33; it++){
        int idx = tid + it*256;
        int row = idx >> 8, c = idx & 255;
        float v = (row == 0) ? qd[c] : (row <= 16 ? W_B[(row-1)*DD + c]
                                                  : W_C[(row-17)*DD + c]);
        sw[row*DD + c] = v;
    }
    float pd0 = pd[0];

    // ---- phase A: h = y @ Win + bin (thread = one d, all 16 tokens) ----
    int d = tid;
    float wcol[PP];
    #pragma unroll
    for (int p = 0; p < PP; p++) wcol[p] = Win[p*DD + d];
    float bi = bin[d];
    __syncthreads();
    #pragma unroll 4
    for (int t = 0; t < 16; t++){
        const float4* yt = (const float4*)&sy[t*PP];
        float h = bi;
        #pragma unroll
        for (int p4 = 0; p4 < 8; p4++){
            float4 yv = yt[p4];
            h = fmaf(wcol[p4*4+0], yv.x, h);
            h = fmaf(wcol[p4*4+1], yv.y, h);
            h = fmaf(wcol[p4*4+2], yv.z, h);
            h = fmaf(wcol[p4*4+3], yv.w, h);
        }
        sh[t*DD + d] = h;
        g_h[(size_t)(tok0 + t)*DD + d] = h;
    }
    __syncthreads();

    // ---- phase LN: warp-per-2-tokens, lane holds 8 d's ----
    int lane = tid & 31, wid = tid >> 5;
    {
        float4 gA = *(const float4*)&ng[lane*8], gB = *(const float4*)&ng[lane*8+4];
        float4 bA = *(const float4*)&nb[lane*8], bB = *(const float4*)&nb[lane*8+4];
        #pragma unroll
        for (int t = 0; t < 2; t++){
            int tok = wid*2 + t;
            float4 h0 = *(const float4*)&sh[tok*DD + lane*8];
            float4 h1 = *(const float4*)&sh[tok*DD + lane*8 + 4];
            float s  = (h0.x+h0.y)+(h0.z+h0.w)+(h1.x+h1.y)+(h1.z+h1.w);
            float s2 = h0.x*h0.x+h0.y*h0.y+h0.z*h0.z+h0.w*h0.w
                     + h1.x*h1.x+h1.y*h1.y+h1.z*h1.z+h1.w*h1.w;
            #pragma unroll
            for (int o = 16; o; o >>= 1){
                s  += __shfl_xor_sync(0xffffffffu, s,  o);
                s2 += __shfl_xor_sync(0xffffffffu, s2, o);
            }
            float mu   = s * (1.f/DD);
            float var  = s2 * (1.f/DD) - mu*mu;
            float rstd = rsqrtf(var + 1e-5f);
            float4 n0, n1;
            n0.x = (h0.x-mu)*rstd*gA.x + bA.x;  n0.y = (h0.y-mu)*rstd*gA.y + bA.y;
            n0.z = (h0.z-mu)*rstd*gA.z + bA.z;  n0.w = (h0.w-mu)*rstd*gA.w + bA.w;
            n1.x = (h1.x-mu)*rstd*gB.x + bB.x;  n1.y = (h1.y-mu)*rstd*gB.y + bB.y;
            n1.z = (h1.z-mu)*rstd*gB.z + bB.z;  n1.w = (h1.w-mu)*rstd*gB.w + bB.w;
            *(float4*)&shn[tok*DD + lane*8]     = n0;
            *(float4*)&shn[tok*DD + lane*8 + 4] = n1;
            *(float4*)&g_hn[(size_t)(tok0+tok)*DD + lane*8]     = n0;
            *(float4*)&g_hn[(size_t)(tok0+tok)*DD + lane*8 + 4] = n1;
        }
    }
    __syncthreads();

    // ---- phase B: thread = (tok, sub); sub covers d = sub*4 + 64j (16 d's)
    //      33 column passes, 2 live accumulators, shfl-reduce over 16 subs ----
    {
        int tok = tid >> 4, sub = tid & 15;
        const float* hrow = &shn[tok*DD];
        ull ha[8];
        #pragma unroll
        for (int j = 0; j < 4; j++){
            float4 hv = *(const float4*)&hrow[sub*4 + 64*j];
            asm("mov.b64 %0, {%1, %2};" : "=l"(ha[2*j])   : "f"(hv.x), "f"(hv.y));
            asm("mov.b64 %0, {%1, %2};" : "=l"(ha[2*j+1]) : "f"(hv.z), "f"(hv.w));
        }
        int tg = tok0 + tok;
        float delta = 0.f, myB = 0.f, myC = 0.f;

        // pass 1: col 0 = q_delta, cols 1..16 = W_B rows
        #pragma unroll
        for (int c = 0; c <= 16; c++){
            ull a0 = 0ull, a1 = 0ull;
            const float* wr = &sw[c*DD];
            #pragma unroll
            for (int j = 0; j < 4; j++){
                ulonglong2 wv = *(const ulonglong2*)&wr[sub*4 + 64*j];
                FFMA2(a0, ha[2*j],   wv.x);
                FFMA2(a1, ha[2*j+1], wv.y);
            }
            float2 u = unpack2(a0), v = unpack2(a1);
            float s = (u.x + u.y) + (v.x + v.y);
            s += __shfl_xor_sync(0xffffffffu, s, 1);
            s += __shfl_xor_sync(0xffffffffu, s, 2);
            s += __shfl_xor_sync(0xffffffffu, s, 4);
            s += __shfl_xor_sync(0xffffffffu, s, 8);
            if (c == 0)            delta = s;
            else if (sub == c - 1) myB   = s;
        }
        delta = softplusf(pd0 + delta);
        g_dB[tg*NXX + sub] = delta * myB;
        if (sub == 0) g_dl2[tg] = delta * 1.44269504088896f;

        // pass 2: cols 17..32 = W_C rows
        #pragma unroll
        for (int c = 17; c < 33; c++){
            ull a0 = 0ull, a1 = 0ull;
            const float* wr = &sw[c*DD];
            #pragma unroll
            for (int j = 0; j < 4; j++){
                ulonglong2 wv = *(const ulonglong2*)&wr[sub*4 + 64*j];
                FFMA2(a0, ha[2*j],   wv.x);
                FFMA2(a1, ha[2*j+1], wv.y);
            }
            float2 u = unpack2(a0), v = unpack2(a1);
            float s = (u.x + u.y) + (v.x + v.y);
            s += __shfl_xor_sync(0xffffffffu, s, 1);
            s += __shfl_xor_sync(0xffffffffu, s, 2);
            s += __shfl_xor_sync(0xffffffffu, s, 4);
            s += __shfl_xor_sync(0xffffffffu, s, 8);
            if (sub == c - 17) myC = s;
        }
        g_C[tg*NXX + sub] = myC;
    }
}

// =====================================================================
// K2: selective scan — grid (16 d-chunks, 8 batches) x 256 thr (16d x 16n)
// register double-buffer of the per-tile inputs to hide LDG latency
// =====================================================================
__global__ void __launch_bounds__(256) k2(const float* __restrict__ A){
    __shared__ float sdl2[32];
    __shared__ float sdb[32*16];
    __shared__ float sc [32*16];
    __shared__ float su [32*16];
    __shared__ float scx[32*256];
    int tid = threadIdx.x;
    int n = tid & 15, dl = tid >> 4;
    int b = blockIdx.y, d0 = blockIdx.x * 16;
    float a = A[(d0 + dl)*NXX + n];
    float x = 0.f;
    size_t tbase = (size_t)b * LL;

    // prefetch tile 0 into registers
    float pdb[2], pc[2], pu[2], pdl = 0.f;
    if (tid < 32) pdl = g_dl2[tbase + tid];
    #pragma unroll
    for (int r = 0; r < 2; r++){
        int idx = tid + r*256;
        int tt = idx >> 4, q = idx & 15;
        pdb[r] = g_dB[(tbase + tt)*NXX + q];
        pc [r] = g_C [(tbase + tt)*NXX + q];
        pu [r] = g_hn[(tbase + tt)*DD + d0 + q];
    }

    for (int t0 = 0; t0 < LL; t0 += 32){
        if (tid < 32) sdl2[tid] = pdl;
        #pragma unroll
        for (int r = 0; r < 2; r++){
            int idx = tid + r*256;
            sdb[idx] = pdb[r]; sc[idx] = pc[r]; su[idx] = pu[r];
        }
        __syncthreads();
        // prefetch next tile (overlaps with compute below)
        if (t0 + 32 < LL){
            int t1 = t0 + 32;
            if (tid < 32) pdl = g_dl2[tbase + t1 + tid];
            #pragma unroll
            for (int r = 0; r < 2; r++){
                int idx = tid + r*256;
                int tt = idx >> 4, q = idx & 15;
                pdb[r] = g_dB[(tbase + t1 + tt)*NXX + q];
                pc [r] = g_C [(tbase + t1 + tt)*NXX + q];
                pu [r] = g_hn[(tbase + t1 + tt)*DD + d0 + q];
            }
        }
        #pragma unroll 4
        for (int tt = 0; tt < 32; tt++){
            float dA  = fexp2(sdl2[tt] * a);
            float dbu = sdb[tt*16 + n] * su[tt*16 + dl];
            x = fmaf(dA, x, dbu);
            scx[tt*256 + dl*16 + n] = x * sc[tt*16 + n];
        }
        __syncthreads();
        #pragma unroll
        for (int r = 0; r < 2; r++){
            int c = tid + r*256;
            int tt = c >> 4, dd = c & 15;
            const float4* p = (const float4*)&scx[tt*256 + dd*16];
            float4 v0 = p[0], v1 = p[1], v2 = p[2], v3 = p[3];
            float s = ((v0.x+v0.y)+(v0.z+v0.w)) + ((v1.x+v1.y)+(v1.z+v1.w))
                    + ((v2.x+v2.y)+(v2.z+v2.w)) + ((v3.x+v3.y)+(v3.z+v3.w));
            g_upd[(tbase + t0 + tt)*DD + d0 + dd] = s;
        }
        __syncthreads();
    }
}

// =====================================================================
// K34: fused  h2 = LN(h+upd) ;  G = gelu(h2@W1+b1) ;  out = G@W2+b2
// 256 blocks (64 tokens each) x 256 threads
// dyn smem: sv[64][260] | Bs[32*256 / W2s 256*32]  = 99328 B
// =====================================================================
#define SVS 260
__global__ void __launch_bounds__(256, 2) k34(const float* __restrict__ nfg,
                                              const float* __restrict__ nfb,
                                              const float* __restrict__ W1,
                                              const float* __restrict__ b1,
                                              const float* __restrict__ W2,
                                              const float* __restrict__ b2,
                                              float* __restrict__ out){
    extern __shared__ float sm3[];
    float* sv = sm3;                 // [64][SVS] : LN result, later gelu result
    float* Bs = sm3 + 64*SVS;        // [32][256] W1 chunk, later [256][32] W2

    int tid  = threadIdx.x;
    int tok0 = blockIdx.x * 64;
    int lane = tid & 31, wrp = tid >> 5;

    // ---- phase 1: LN(h + upd) -> sv. warp wrp handles tokens wrp*8..+7 ----
    {
        float4 gA = *(const float4*)&nfg[lane*8], gB = *(const float4*)&nfg[lane*8+4];
        float4 bA = *(const float4*)&nfb[lane*8], bB = *(const float4*)&nfb[lane*8+4];
        #pragma unroll
        for (int t = 0; t < 8; t++){
            int tok = wrp*8 + t;
            size_t base = (size_t)(tok0 + tok)*DD + lane*8;
            float4 h0 = *(const float4*)&g_h[base];
            float4 h1 = *(const float4*)&g_h[base+4];
            float4 u0 = *(const float4*)&g_upd[base];
            float4 u1 = *(const float4*)&g_upd[base+4];
            float4 v0, v1;
            v0.x=h0.x+u0.x; v0.y=h0.y+u0.y; v0.z=h0.z+u0.z; v0.w=h0.w+u0.w;
            v1.x=h1.x+u1.x; v1.y=h1.y+u1.y; v1.z=h1.z+u1.z; v1.w=h1.w+u1.w;
            float s  = (v0.x+v0.y)+(v0.z+v0.w)+(v1.x+v1.y)+(v1.z+v1.w);
            float s2 = v0.x*v0.x+v0.y*v0.y+v0.z*v0.z+v0.w*v0.w
                     + v1.x*v1.x+v1.y*v1.y+v1.z*v1.z+v1.w*v1.w;
            #pragma unroll
            for (int o = 16; o; o >>= 1){
                s  += __shfl_xor_sync(0xffffffffu, s,  o);
                s2 += __shfl_xor_sync(0xffffffffu, s2, o);
            }
            float mu   = s * (1.f/DD);
            float var  = s2 * (1.f/DD) - mu*mu;
            float rstd = rsqrtf(var + 1e-5f);
            float4 n0, n1;
            n0.x=(v0.x-mu)*rstd*gA.x+bA.x; n0.y=(v0.y-mu)*rstd*gA.y+bA.y;
            n0.z=(v0.z-mu)*rstd*gA.z+bA.z; n0.w=(v0.w-mu)*rstd*gA.w+bA.w;
            n1.x=(v1.x-mu)*rstd*gB.x+bB.x; n1.y=(v1.y-mu)*rstd*gB.y+bB.y;
            n1.z=(v1.z-mu)*rstd*gB.z+bB.z; n1.w=(v1.w-mu)*rstd*gB.w+bB.w;
            *(float4*)&sv[tok*SVS + lane*8]     = n0;
            *(float4*)&sv[tok*SVS + lane*8 + 4] = n1;
        }
    }
    __syncthreads();

    // ---- phase 2: G = gelu(sv @ W1 + b1), tile 64x256 ----
    // lane handles cols {tx*4..+3} and {128+tx*4..+3}  (conflict-free LDS.128)
    int tx = tid & 31, ty = tid >> 5;          // toks ty*8..+7
    ull acc[8][4];
    #pragma unroll
    for (int i = 0; i < 8; i++)
        #pragma unroll
        for (int j = 0; j < 4; j++) acc[i][j] = 0ull;

    for (int kk = 0; kk < DD; kk += 32){
        #pragma unroll
        for (int r = 0; r < 8; r++){
            int f4 = tid + r*256;
            int row = f4 >> 6, c4 = (f4 & 63) << 2;
            *(float4*)&Bs[row*256 + c4] =
                *(const float4*)&W1[(size_t)(kk + row)*DD + c4];
        }
        __syncthreads();
        #pragma unroll 8
        for (int k = 0; k < 32; k++){
            ulonglong2 p0 = *(const ulonglong2*)&Bs[k*256 + tx*4];
            ulonglong2 p1 = *(const ulonglong2*)&Bs[k*256 + 128 + tx*4];
            #pragma unroll
            for (int i = 0; i < 8; i++){
                ull a2 = packdup(sv[(ty*8+i)*SVS + kk + k]);
                FFMA2(acc[i][0], a2, p0.x);
                FFMA2(acc[i][1], a2, p0.y);
                FFMA2(acc[i][2], a2, p1.x);
                FFMA2(acc[i][3], a2, p1.y);
            }
        }
        __syncthreads();
    }

    // gelu + bias -> back into sv (aliased as G)
    {
        float4 bb0 = *(const float4*)&b1[tx*4];
        float4 bb1 = *(const float4*)&b1[128 + tx*4];
        float bias[8] = {bb0.x,bb0.y,bb0.z,bb0.w,bb1.x,bb1.y,bb1.z,bb1.w};
        #pragma unroll
        for (int i = 0; i < 8; i++){
            int tok = ty*8 + i;
            #pragma unroll
            for (int j = 0; j < 4; j++){
                float2 u = unpack2(acc[i][j]);
                float2 o;
                o.x = geluf(u.x + bias[2*j]);
                o.y = geluf(u.y + bias[2*j+1]);
                int colbase = (j < 2) ? (tx*4 + 2*j) : (128 + tx*4 + 2*(j-2));
                *(float2*)&sv[tok*SVS + colbase] = o;
            }
        }
    }
    // load W2 into Bs region (linear copy, [256][32])
    #pragma unroll
    for (int r = 0; r < 8; r++){
        int f4 = (tid + r*256) << 2;
        *(float4*)&Bs[f4] = *(const float4*)&W2[f4];
    }
    __syncthreads();

    // ---- phase 3: out = G @ W2 + b2 ; thread = (tok, 8-out group) ----
    {
        int tok = tid >> 2, og = tid & 3;
        float4 c0 = *(const float4*)&b2[og*8];
        float4 c1 = *(const float4*)&b2[og*8 + 4];
        ull o0, o1, o2, o3;
        asm("mov.b64 %0, {%1, %2};" : "=l"(o0) : "f"(c0.x), "f"(c0.y));
        asm("mov.b64 %0, {%1, %2};" : "=l"(o1) : "f"(c0.z), "f"(c0.w));
        asm("mov.b64 %0, {%1, %2};" : "=l"(o2) : "f"(c1.x), "f"(c1.y));
        asm("mov.b64 %0, {%1, %2};" : "=l"(o3) : "f"(c1.z), "f"(c1.w));
        #pragma unroll 4
        for (int k4 = 0; k4 < DD; k4 += 4){
            float4 g4 = *(const float4*)&sv[tok*SVS + k4];
            float ge[4] = {g4.x, g4.y, g4.z, g4.w};
            #pragma unroll
            for (int e = 0; e < 4; e++){
                ull a2 = packdup(ge[e]);
                const ull* wr = (const ull*)&Bs[(k4 + e)*32 + og*8];
                FFMA2(o0, a2, wr[0]);
                FFMA2(o1, a2, wr[1]);
                FFMA2(o2, a2, wr[2]);
                FFMA2(o3, a2, wr[3]);
            }
        }
        float2 r0 = unpack2(o0), r1 = unpack2(o1), r2 = unpack2(o2), r3 = unpack2(o3);
        float4 w0; w0.x=r0.x; w0.y=r0.y; w0.z=r1.x; w0.w=r1.y;
        float4 w1; w1.x=r2.x; w1.y=r2.y; w1.z=r3.x; w1.w=r3.y;
        size_t ob = (size_t)(tok0 + tok)*32 + og*8;
        *(float4*)&out[ob]     = w0;
        *(float4*)&out[ob + 4] = w1;
    }
}

// ---------------- launcher ----------------
extern "C" void kernel_launch(void* const* d_in, const int* in_sizes, int n_in,
                              void* d_out, int out_size){
    (void)in_sizes; (void)n_in; (void)out_size;
    const float* y    = (const float*)d_in[0];
    const float* Win  = (const float*)d_in[1];
    const float* bin_ = (const float*)d_in[2];
    const float* ng   = (const float*)d_in[3];
    const float* nb   = (const float*)d_in[4];
    const float* A    = (const float*)d_in[5];
    const float* W_B  = (const float*)d_in[6];
    const float* W_C  = (const float*)d_in[7];
    const float* qd   = (const float*)d_in[8];
    const float* pd   = (const float*)d_in[9];
    const float* nfg  = (const float*)d_in[10];
    const float* nfb  = (const float*)d_in[11];
    const float* W1   = (const float*)d_in[12];
    const float* b1   = (const float*)d_in[13];
    const float* W2   = (const float*)d_in[14];
    const float* b2   = (const float*)d_in[15];
    float* out = (float*)d_out;

    cudaFuncSetAttribute(k1ab, cudaFuncAttributeMaxDynamicSharedMemorySize, 68608);
    cudaFuncSetAttribute(k34,  cudaFuncAttributeMaxDynamicSharedMemorySize, 99328);

    k1ab<<<NT/16, 256, 68608>>>(y, Win, bin_, ng, nb, W_B, W_C, qd, pd);
    k2  <<<dim3(DD/16, BB), 256>>>(A);
    k34 <<<NT/64, 256, 99328>>>(nfg, nfb, W1, b1, W2, b2, out);
}

// round 15
// speedup vs baseline: 1.1050x; 1.0046x over previous
#include <cuda_runtime.h>
#include <cuda_bf16.h>
#include <cstdint>

#define BB 8
#define LL 2048
#define PP 32
#define DD 256
#define NXX 16
#define NT (BB*LL)   // 16384 tokens

typedef unsigned long long ull;

// ---------------- scratch (device globals; no allocation allowed) ----------------
__device__ float g_h  [NT*DD];
__device__ float g_hn [NT*DD];
__device__ float g_dl2[NT];        // delta * log2(e)
__device__ float g_dB [NT*NXX];    // delta * Bm
__device__ float g_C  [NT*NXX];
__device__ float g_upd[NT*DD];

// ---------------- helpers ----------------
__device__ __forceinline__ float fexp2(float x){
    float r; asm("ex2.approx.f32 %0, %1;" : "=f"(r) : "f"(x)); return r;
}
__device__ __forceinline__ float softplusf(float x){
    return x > 20.f ? x : log1pf(expf(x));
}
__device__ __forceinline__ float geluf(float x){
    return 0.5f * x * (1.f + erff(x * 0.70710678118654752f));
}
__device__ __forceinline__ ull packdup(float v){
    ull r; asm("mov.b64 %0, {%1, %1};" : "=l"(r) : "f"(v)); return r;
}
#define FFMA2(acc, a, b) asm("fma.rn.f32x2 %0, %1, %2, %0;" : "+l"(acc) : "l"(a), "l"(b))
__device__ __forceinline__ float2 unpack2(ull p){
    float lo, hi; asm("mov.b64 {%0, %1}, %2;" : "=f"(lo), "=f"(hi) : "l"(p));
    float2 r; r.x = lo; r.y = hi; return r;
}

// =====================================================================
// K1: fused  h = y@Win + bin ;  hn = LN(h) ;  [delta | B | C] = proj(hn)
// 1024 blocks x 256 threads, 16 tokens/block
// dyn smem (floats): sy[512] | sh[4096] | shn[4096] | sw[33*256]
//   = 17152 floats = 68608 B
// =====================================================================
__global__ void __launch_bounds__(256, 3) k1ab(const float* __restrict__ y,
                                               const float* __restrict__ Win,
                                               const float* __restrict__ bin,
                                               const float* __restrict__ ng,
                                               const float* __restrict__ nb,
                                               const float* __restrict__ W_B,
                                               const float* __restrict__ W_C,
                                               const float* __restrict__ qd,
                                               const float* __restrict__ pd){
    extern __shared__ float sm1[];
    float* sy  = sm1;               // [16][32]
    float* sh  = sm1 + 512;         // [16][256]
    float* shn = sm1 + 4608;        // [16][256]
    float* sw  = sm1 + 8704;        // [33][256]  row0=q_delta, 1..16=W_B, 17..32=W_C

    int tid  = threadIdx.x;
    int tok0 = blockIdx.x * 16;

    // ---- load y tile + projection weights (plain row-major, coalesced) ----
    sy[tid]       = y[(size_t)tok0*PP + tid];
    sy[tid + 256] = y[(size_t)tok0*PP + tid + 256];
    #pragma unroll
    for (int it = 0; it < 33; it++){
        int idx = tid + it*256;
        int row = idx >> 8, c = idx & 255;
        float v = (row == 0) ? qd[c] : (row <= 16 ? W_B[(row-1)*DD + c]
                                                  : W_C[(row-17)*DD + c]);
        sw[row*DD + c] = v;
    }
    float pd0 = pd[0];

    // ---- phase A: h = y @ Win + bin (thread = one d, all 16 tokens) ----
    int d = tid;
    float wcol[PP];
    #pragma unroll
    for (int p = 0; p < PP; p++) wcol[p] = Win[p*DD + d];
    float bi = bin[d];
    __syncthreads();
    #pragma unroll 4
    for (int t = 0; t < 16; t++){
        const float4* yt = (const float4*)&sy[t*PP];
        float h = bi;
        #pragma unroll
        for (int p4 = 0; p4 < 8; p4++){
            float4 yv = yt[p4];
            h = fmaf(wcol[p4*4+0], yv.x, h);
            h = fmaf(wcol[p4*4+1], yv.y, h);
            h = fmaf(wcol[p4*4+2], yv.z, h);
            h = fmaf(wcol[p4*4+3], yv.w, h);
        }
        sh[t*DD + d] = h;
        g_h[(size_t)(tok0 + t)*DD + d] = h;
    }
    __syncthreads();

    // ---- phase LN: warp-per-2-tokens, lane holds 8 d's ----
    int lane = tid & 31, wid = tid >> 5;
    {
        float4 gA = *(const float4*)&ng[lane*8], gB = *(const float4*)&ng[lane*8+4];
        float4 bA = *(const float4*)&nb[lane*8], bB = *(const float4*)&nb[lane*8+4];
        #pragma unroll
        for (int t = 0; t < 2; t++){
            int tok = wid*2 + t;
            float4 h0 = *(const float4*)&sh[tok*DD + lane*8];
            float4 h1 = *(const float4*)&sh[tok*DD + lane*8 + 4];
            float s  = (h0.x+h0.y)+(h0.z+h0.w)+(h1.x+h1.y)+(h1.z+h1.w);
            float s2 = h0.x*h0.x+h0.y*h0.y+h0.z*h0.z+h0.w*h0.w
                     + h1.x*h1.x+h1.y*h1.y+h1.z*h1.z+h1.w*h1.w;
            #pragma unroll
            for (int o = 16; o; o >>= 1){
                s  += __shfl_xor_sync(0xffffffffu, s,  o);
                s2 += __shfl_xor_sync(0xffffffffu, s2, o);
            }
            float mu   = s * (1.f/DD);
            float var  = s2 * (1.f/DD) - mu*mu;
            float rstd = rsqrtf(var + 1e-5f);
            float4 n0, n1;
            n0.x = (h0.x-mu)*rstd*gA.x + bA.x;  n0.y = (h0.y-mu)*rstd*gA.y + bA.y;
            n0.z = (h0.z-mu)*rstd*gA.z + bA.z;  n0.w = (h0.w-mu)*rstd*gA.w + bA.w;
            n1.x = (h1.x-mu)*rstd*gB.x + bB.x;  n1.y = (h1.y-mu)*rstd*gB.y + bB.y;
            n1.z = (h1.z-mu)*rstd*gB.z + bB.z;  n1.w = (h1.w-mu)*rstd*gB.w + bB.w;
            *(float4*)&shn[tok*DD + lane*8]     = n0;
            *(float4*)&shn[tok*DD + lane*8 + 4] = n1;
            *(float4*)&g_hn[(size_t)(tok0+tok)*DD + lane*8]     = n0;
            *(float4*)&g_hn[(size_t)(tok0+tok)*DD + lane*8 + 4] = n1;
        }
    }
    __syncthreads();

    // ---- phase B: thread = (tok, sub); sub covers d = sub*4 + 64j (16 d's)
    //      33 column passes, 2 live accumulators, shfl-reduce over 16 subs ----
    {
        int tok = tid >> 4, sub = tid & 15;
        const float* hrow = &shn[tok*DD];
        ull ha[8];
        #pragma unroll
        for (int j = 0; j < 4; j++){
            float4 hv = *(const float4*)&hrow[sub*4 + 64*j];
            asm("mov.b64 %0, {%1, %2};" : "=l"(ha[2*j])   : "f"(hv.x), "f"(hv.y));
            asm("mov.b64 %0, {%1, %2};" : "=l"(ha[2*j+1]) : "f"(hv.z), "f"(hv.w));
        }
        int tg = tok0 + tok;
        float delta = 0.f, myB = 0.f, myC = 0.f;

        // pass 1: col 0 = q_delta, cols 1..16 = W_B rows
        #pragma unroll
        for (int c = 0; c <= 16; c++){
            ull a0 = 0ull, a1 = 0ull;
            const float* wr = &sw[c*DD];
            #pragma unroll
            for (int j = 0; j < 4; j++){
                ulonglong2 wv = *(const ulonglong2*)&wr[sub*4 + 64*j];
                FFMA2(a0, ha[2*j],   wv.x);
                FFMA2(a1, ha[2*j+1], wv.y);
            }
            float2 u = unpack2(a0), v = unpack2(a1);
            float s = (u.x + u.y) + (v.x + v.y);
            s += __shfl_xor_sync(0xffffffffu, s, 1);
            s += __shfl_xor_sync(0xffffffffu, s, 2);
            s += __shfl_xor_sync(0xffffffffu, s, 4);
            s += __shfl_xor_sync(0xffffffffu, s, 8);
            if (c == 0)            delta = s;
            else if (sub == c - 1) myB   = s;
        }
        delta = softplusf(pd0 + delta);
        g_dB[tg*NXX + sub] = delta * myB;
        if (sub == 0) g_dl2[tg] = delta * 1.44269504088896f;

        // pass 2: cols 17..32 = W_C rows
        #pragma unroll
        for (int c = 17; c < 33; c++){
            ull a0 = 0ull, a1 = 0ull;
            const float* wr = &sw[c*DD];
            #pragma unroll
            for (int j = 0; j < 4; j++){
                ulonglong2 wv = *(const ulonglong2*)&wr[sub*4 + 64*j];
                FFMA2(a0, ha[2*j],   wv.x);
                FFMA2(a1, ha[2*j+1], wv.y);
            }
            float2 u = unpack2(a0), v = unpack2(a1);
            float s = (u.x + u.y) + (v.x + v.y);
            s += __shfl_xor_sync(0xffffffffu, s, 1);
            s += __shfl_xor_sync(0xffffffffu, s, 2);
            s += __shfl_xor_sync(0xffffffffu, s, 4);
            s += __shfl_xor_sync(0xffffffffu, s, 8);
            if (sub == c - 17) myC = s;
        }
        g_C[tg*NXX + sub] = myC;
    }
}

// =====================================================================
// K2: selective scan — grid (16 d-chunks, 8 batches) x 256 thr (16d x 16n)
// register double-buffer of the per-tile inputs to hide LDG latency
// =====================================================================
__global__ void __launch_bounds__(256) k2(const float* __restrict__ A){
    __shared__ float sdl2[32];
    __shared__ float sdb[32*16];
    __shared__ float sc [32*16];
    __shared__ float su [32*16];
    __shared__ float scx[32*256];
    int tid = threadIdx.x;
    int n = tid & 15, dl = tid >> 4;
    int b = blockIdx.y, d0 = blockIdx.x * 16;
    float a = A[(d0 + dl)*NXX + n];
    float x = 0.f;
    size_t tbase = (size_t)b * LL;

    // prefetch tile 0 into registers
    float pdb[2], pc[2], pu[2], pdl = 0.f;
    if (tid < 32) pdl = g_dl2[tbase + tid];
    #pragma unroll
    for (int r = 0; r < 2; r++){
        int idx = tid + r*256;
        int tt = idx >> 4, q = idx & 15;
        pdb[r] = g_dB[(tbase + tt)*NXX + q];
        pc [r] = g_C [(tbase + tt)*NXX + q];
        pu [r] = g_hn[(tbase + tt)*DD + d0 + q];
    }

    for (int t0 = 0; t0 < LL; t0 += 32){
        if (tid < 32) sdl2[tid] = pdl;
        #pragma unroll
        for (int r = 0; r < 2; r++){
            int idx = tid + r*256;
            sdb[idx] = pdb[r]; sc[idx] = pc[r]; su[idx] = pu[r];
        }
        __syncthreads();
        // prefetch next tile (overlaps with compute below)
        if (t0 + 32 < LL){
            int t1 = t0 + 32;
            if (tid < 32) pdl = g_dl2[tbase + t1 + tid];
            #pragma unroll
            for (int r = 0; r < 2; r++){
                int idx = tid + r*256;
                int tt = idx >> 4, q = idx & 15;
                pdb[r] = g_dB[(tbase + t1 + tt)*NXX + q];
                pc [r] = g_C [(tbase + t1 + tt)*NXX + q];
                pu [r] = g_hn[(tbase + t1 + tt)*DD + d0 + q];
            }
        }
        #pragma unroll 4
        for (int tt = 0; tt < 32; tt++){
            float dA  = fexp2(sdl2[tt] * a);
            float dbu = sdb[tt*16 + n] * su[tt*16 + dl];
            x = fmaf(dA, x, dbu);
            scx[tt*256 + dl*16 + n] = x * sc[tt*16 + n];
        }
        __syncthreads();
        #pragma unroll
        for (int r = 0; r < 2; r++){
            int c = tid + r*256;
            int tt = c >> 4, dd = c & 15;
            const float4* p = (const float4*)&scx[tt*256 + dd*16];
            float4 v0 = p[0], v1 = p[1], v2 = p[2], v3 = p[3];
            float s = ((v0.x+v0.y)+(v0.z+v0.w)) + ((v1.x+v1.y)+(v1.z+v1.w))
                    + ((v2.x+v2.y)+(v2.z+v2.w)) + ((v3.x+v3.y)+(v3.z+v3.w));
            g_upd[(tbase + t0 + tt)*DD + d0 + dd] = s;
        }
        __syncthreads();
    }
}

// =====================================================================
// K34: fused  h2 = LN(h+upd) ;  G = gelu(h2@W1+b1) ;  out = G@W2+b2
// 256 blocks (64 tokens each) x 256 threads
// dyn smem: sv[64][260] | Bs[32*256 / W2s 256*32]  = 99328 B
// =====================================================================
#define SVS 260
__global__ void __launch_bounds__(256, 2) k34(const float* __restrict__ nfg,
                                              const float* __restrict__ nfb,
                                              const float* __restrict__ W1,
                                              const float* __restrict__ b1,
                                              const float* __restrict__ W2,
                                              const float* __restrict__ b2,
                                              float* __restrict__ out){
    extern __shared__ float sm3[];
    float* sv = sm3;                 // [64][SVS] : LN result, later gelu result
    float* Bs = sm3 + 64*SVS;        // [32][256] W1 chunk, later [256][32] W2

    int tid  = threadIdx.x;
    int tok0 = blockIdx.x * 64;
    int lane = tid & 31, wrp = tid >> 5;

    // ---- phase 1: LN(h + upd) -> sv. warp wrp handles tokens wrp*8..+7 ----
    {
        float4 gA = *(const float4*)&nfg[lane*8], gB = *(const float4*)&nfg[lane*8+4];
        float4 bA = *(const float4*)&nfb[lane*8], bB = *(const float4*)&nfb[lane*8+4];
        #pragma unroll
        for (int t = 0; t < 8; t++){
            int tok = wrp*8 + t;
            size_t base = (size_t)(tok0 + tok)*DD + lane*8;
            float4 h0 = *(const float4*)&g_h[base];
            float4 h1 = *(const float4*)&g_h[base+4];
            float4 u0 = *(const float4*)&g_upd[base];
            float4 u1 = *(const float4*)&g_upd[base+4];
            float4 v0, v1;
            v0.x=h0.x+u0.x; v0.y=h0.y+u0.y; v0.z=h0.z+u0.z; v0.w=h0.w+u0.w;
            v1.x=h1.x+u1.x; v1.y=h1.y+u1.y; v1.z=h1.z+u1.z; v1.w=h1.w+u1.w;
            float s  = (v0.x+v0.y)+(v0.z+v0.w)+(v1.x+v1.y)+(v1.z+v1.w);
            float s2 = v0.x*v0.x+v0.y*v0.y+v0.z*v0.z+v0.w*v0.w
                     + v1.x*v1.x+v1.y*v1.y+v1.z*v1.z+v1.w*v1.w;
            #pragma unroll
            for (int o = 16; o; o >>= 1){
                s  += __shfl_xor_sync(0xffffffffu, s,  o);
                s2 += __shfl_xor_sync(0xffffffffu, s2, o);
            }
            float mu   = s * (1.f/DD);
            float var  = s2 * (1.f/DD) - mu*mu;
            float rstd = rsqrtf(var + 1e-5f);
            float4 n0, n1;
            n0.x=(v0.x-mu)*rstd*gA.x+bA.x; n0.y=(v0.y-mu)*rstd*gA.y+bA.y;
            n0.z=(v0.z-mu)*rstd*gA.z+bA.z; n0.w=(v0.w-mu)*rstd*gA.w+bA.w;
            n1.x=(v1.x-mu)*rstd*gB.x+bB.x; n1.y=(v1.y-mu)*rstd*gB.y+bB.y;
            n1.z=(v1.z-mu)*rstd*gB.z+bB.z; n1.w=(v1.w-mu)*rstd*gB.w+bB.w;
            *(float4*)&sv[tok*SVS + lane*8]     = n0;
            *(float4*)&sv[tok*SVS + lane*8 + 4] = n1;
        }
    }
    __syncthreads();

    // ---- phase 2: G = gelu(sv @ W1 + b1), tile 64x256 ----
    // lane handles cols {tx*4..+3} and {128+tx*4..+3}  (conflict-free LDS.128)
    int tx = tid & 31, ty = tid >> 5;          // toks ty*8..+7
    ull acc[8][4];
    #pragma unroll
    for (int i = 0; i < 8; i++)
        #pragma unroll
        for (int j = 0; j < 4; j++) acc[i][j] = 0ull;

    for (int kk = 0; kk < DD; kk += 32){
        #pragma unroll
        for (int r = 0; r < 8; r++){
            int f4 = tid + r*256;
            int row = f4 >> 6, c4 = (f4 & 63) << 2;
            *(float4*)&Bs[row*256 + c4] =
                *(const float4*)&W1[(size_t)(kk + row)*DD + c4];
        }
        __syncthreads();
        #pragma unroll 8
        for (int k = 0; k < 32; k++){
            ulonglong2 p0 = *(const ulonglong2*)&Bs[k*256 + tx*4];
            ulonglong2 p1 = *(const ulonglong2*)&Bs[k*256 + 128 + tx*4];
            #pragma unroll
            for (int i = 0; i < 8; i++){
                ull a2 = packdup(sv[(ty*8+i)*SVS + kk + k]);
                FFMA2(acc[i][0], a2, p0.x);
                FFMA2(acc[i][1], a2, p0.y);
                FFMA2(acc[i][2], a2, p1.x);
                FFMA2(acc[i][3], a2, p1.y);
            }
        }
        __syncthreads();
    }

    // gelu + bias -> back into sv (aliased as G)
    {
        float4 bb0 = *(const float4*)&b1[tx*4];
        float4 bb1 = *(const float4*)&b1[128 + tx*4];
        float bias[8] = {bb0.x,bb0.y,bb0.z,bb0.w,bb1.x,bb1.y,bb1.z,bb1.w};
        #pragma unroll
        for (int i = 0; i < 8; i++){
            int tok = ty*8 + i;
            #pragma unroll
            for (int j = 0; j < 4; j++){
                float2 u = unpack2(acc[i][j]);
                float2 o;
                o.x = geluf(u.x + bias[2*j]);
                o.y = geluf(u.y + bias[2*j+1]);
                int colbase = (j < 2) ? (tx*4 + 2*j) : (128 + tx*4 + 2*(j-2));
                *(float2*)&sv[tok*SVS + colbase] = o;
            }
        }
    }
    // load W2 into Bs region (linear copy, [256][32])
    #pragma unroll
    for (int r = 0; r < 8; r++){
        int f4 = (tid + r*256) << 2;
        *(float4*)&Bs[f4] = *(const float4*)&W2[f4];
    }
    __syncthreads();

    // ---- phase 3: out = G @ W2 + b2 ; thread = (tok, 8-out group) ----
    {
        int tok = tid >> 2, og = tid & 3;
        float4 c0 = *(const float4*)&b2[og*8];
        float4 c1 = *(const float4*)&b2[og*8 + 4];
        ull o0, o1, o2, o3;
        asm("mov.b64 %0, {%1, %2};" : "=l"(o0) : "f"(c0.x), "f"(c0.y));
        asm("mov.b64 %0, {%1, %2};" : "=l"(o1) : "f"(c0.z), "f"(c0.w));
        asm("mov.b64 %0, {%1, %2};" : "=l"(o2) : "f"(c1.x), "f"(c1.y));
        asm("mov.b64 %0, {%1, %2};" : "=l"(o3) : "f"(c1.z), "f"(c1.w));
        #pragma unroll 4
        for (int k4 = 0; k4 < DD; k4 += 4){
            float4 g4 = *(const float4*)&sv[tok*SVS + k4];
            float ge[4] = {g4.x, g4.y, g4.z, g4.w};
            #pragma unroll
            for (int e = 0; e < 4; e++){
                ull a2 = packdup(ge[e]);
                const ull* wr = (const ull*)&Bs[(k4 + e)*32 + og*8];
                FFMA2(o0, a2, wr[0]);
                FFMA2(o1, a2, wr[1]);
                FFMA2(o2, a2, wr[2]);
                FFMA2(o3, a2, wr[3]);
            }
        }
        float2 r0 = unpack2(o0), r1 = unpack2(o1), r2 = unpack2(o2), r3 = unpack2(o3);
        float4 w0; w0.x=r0.x; w0.y=r0.y; w0.z=r1.x; w0.w=r1.y;
        float4 w1; w1.x=r2.x; w1.y=r2.y; w1.z=r3.x; w1.w=r3.y;
        size_t ob = (size_t)(tok0 + tok)*32 + og*8;
        *(float4*)&out[ob]     = w0;
        *(float4*)&out[ob + 4] = w1;
    }
}

// ---------------- launcher ----------------
extern "C" void kernel_launch(void* const* d_in, const int* in_sizes, int n_in,
                              void* d_out, int out_size){
    (void)in_sizes; (void)n_in; (void)out_size;
    const float* y    = (const float*)d_in[0];
    const float* Win  = (const float*)d_in[1];
    const float* bin_ = (const float*)d_in[2];
    const float* ng   = (const float*)d_in[3];
    const float* nb   = (const float*)d_in[4];
    const float* A    = (const float*)d_in[5];
    const float* W_B  = (const float*)d_in[6];
    const float* W_C  = (const float*)d_in[7];
    const float* qd   = (const float*)d_in[8];
    const float* pd   = (const float*)d_in[9];
    const float* nfg  = (const float*)d_in[10];
    const float* nfb  = (const float*)d_in[11];
    const float* W1   = (const float*)d_in[12];
    const float* b1   = (const float*)d_in[13];
    const float* W2   = (const float*)d_in[14];
    const float* b2   = (const float*)d_in[15];
    float* out = (float*)d_out;

    cudaFuncSetAttribute(k1ab, cudaFuncAttributeMaxDynamicSharedMemorySize, 68608);
    cudaFuncSetAttribute(k34,  cudaFuncAttributeMaxDynamicSharedMemorySize, 99328);

    k1ab<<<NT/16, 256, 68608>>>(y, Win, bin_, ng, nb, W_B, W_C, qd, pd);
    k2  <<<dim3(DD/16, BB), 256>>>(A);
    k34 <<<NT/64, 256, 99328>>>(nfg, nfb, W1, b1, W2, b2, out);
}